// round 2
// baseline (speedup 1.0000x reference)
#include <cuda_runtime.h>
#include <cuda_bf16.h>

#define N_OPT 16
#define OUT_F 1024
#define IN_F  1024
#define BATCH 8
#define A_DIM 512

// ---- scratch (device globals: no alloc in kernel_launch) ----
__device__ float g_wmix[BATCH * OUT_F * IN_F];   // 32 MB: per-batch mixed weights [b][i][j]
__device__ float g_bmix[BATCH * OUT_F];          // per-batch mixed bias

// ============================================================
// Kernel 1: w_mixed[b][i][j] = sum_n sp[b][n] * W[n][i][j]
// Each thread owns one float4 position of the [OUT_F*IN_F] plane,
// reads the 16 expert values ONCE, accumulates all 8 batches.
// Traffic: 64 MB read + 32 MB write.
// ============================================================
__global__ void mix_weights_kernel(const float* __restrict__ W,
                                   const float* __restrict__ sp) {
    __shared__ float s_sp[BATCH * N_OPT];
    if (threadIdx.x < BATCH * N_OPT) s_sp[threadIdx.x] = sp[threadIdx.x];
    __syncthreads();

    const int t = blockIdx.x * blockDim.x + threadIdx.x;    // float4 index in plane
    const int plane4 = (OUT_F * IN_F) / 4;                  // 262144
    if (t >= plane4) return;

    const float4* W4 = reinterpret_cast<const float4*>(W);

    float4 acc[BATCH];
#pragma unroll
    for (int b = 0; b < BATCH; b++) acc[b] = make_float4(0.f, 0.f, 0.f, 0.f);

#pragma unroll
    for (int n = 0; n < N_OPT; n++) {
        float4 w = W4[(size_t)n * plane4 + t];
#pragma unroll
        for (int b = 0; b < BATCH; b++) {
            float s = s_sp[b * N_OPT + n];
            acc[b].x += s * w.x;
            acc[b].y += s * w.y;
            acc[b].z += s * w.z;
            acc[b].w += s * w.w;
        }
    }

    float4* out4 = reinterpret_cast<float4*>(g_wmix);
#pragma unroll
    for (int b = 0; b < BATCH; b++) out4[(size_t)b * plane4 + t] = acc[b];
}

// ============================================================
// Kernel 2: b_mixed[b][i] = sum_n sp[b][n] * bias[n][i]
// ============================================================
__global__ void mix_bias_kernel(const float* __restrict__ bias,
                                const float* __restrict__ sp) {
    int tid = blockIdx.x * blockDim.x + threadIdx.x;   // [0, BATCH*OUT_F)
    if (tid >= BATCH * OUT_F) return;
    int b = tid / OUT_F;
    int i = tid % OUT_F;
    float acc = 0.f;
#pragma unroll
    for (int n = 0; n < N_OPT; n++) acc += sp[b * N_OPT + n] * bias[n * OUT_F + i];
    g_bmix[tid] = acc;
}

// ============================================================
// Kernel 3: batched SGEMM (NT): out[b][a][i] = sum_j x[b][a][j]*w_mixed[b][i][j] + b_mixed[b][i]
// Tiles: BM=128 (a), BN=128 (i), BK=16 (j). 256 threads, 8x8 per thread.
// ============================================================
#define BM 128
#define BN 128
#define BK 16

__global__ void __launch_bounds__(256, 2)
gemm_kernel(const float* __restrict__ x, float* __restrict__ out) {
    const int b  = blockIdx.z;
    const float* Ag = x + (size_t)b * A_DIM * IN_F;                 // [512,1024]
    const float* Bg = g_wmix + (size_t)b * OUT_F * IN_F;            // [1024,1024]

    __shared__ float As[BK][BM + 1];
    __shared__ float Bs[BK][BN + 1];

    const int tid = threadIdx.x;
    const int tx = tid & 15;       // 0..15 -> N direction
    const int ty = tid >> 4;       // 0..15 -> M direction

    const int rowA0 = blockIdx.y * BM;    // a offset
    const int rowB0 = blockIdx.x * BN;    // i offset

    float acc[8][8];
#pragma unroll
    for (int m = 0; m < 8; m++)
#pragma unroll
        for (int n = 0; n < 8; n++) acc[m][n] = 0.f;

    for (int k0 = 0; k0 < IN_F; k0 += BK) {
        // load tiles: 128 rows x 16 cols = 512 float4 each; 256 threads x 2
#pragma unroll
        for (int i = 0; i < 2; i++) {
            int idx = tid + i * 256;          // 0..511
            int r   = idx >> 2;               // 0..127
            int c4  = idx & 3;                // 0..3
            float4 va = *reinterpret_cast<const float4*>(
                Ag + (size_t)(rowA0 + r) * IN_F + k0 + c4 * 4);
            As[c4 * 4 + 0][r] = va.x;
            As[c4 * 4 + 1][r] = va.y;
            As[c4 * 4 + 2][r] = va.z;
            As[c4 * 4 + 3][r] = va.w;
            float4 vb = *reinterpret_cast<const float4*>(
                Bg + (size_t)(rowB0 + r) * IN_F + k0 + c4 * 4);
            Bs[c4 * 4 + 0][r] = vb.x;
            Bs[c4 * 4 + 1][r] = vb.y;
            Bs[c4 * 4 + 2][r] = vb.z;
            Bs[c4 * 4 + 3][r] = vb.w;
        }
        __syncthreads();

#pragma unroll
        for (int k = 0; k < BK; k++) {
            float af[8], bf[8];
#pragma unroll
            for (int m = 0; m < 8; m++) af[m] = As[k][ty * 8 + m];
#pragma unroll
            for (int n = 0; n < 8; n++) bf[n] = Bs[k][tx * 8 + n];
#pragma unroll
            for (int m = 0; m < 8; m++)
#pragma unroll
                for (int n = 0; n < 8; n++) acc[m][n] += af[m] * bf[n];
        }
        __syncthreads();
    }

    // epilogue: add mixed bias, vectorized stores
    const float* bm = g_bmix + (size_t)b * OUT_F;
    float bb[8];
#pragma unroll
    for (int n = 0; n < 8; n++) bb[n] = bm[rowB0 + tx * 8 + n];

    float* Og = out + (size_t)b * A_DIM * OUT_F;
#pragma unroll
    for (int m = 0; m < 8; m++) {
        float* row = Og + (size_t)(rowA0 + ty * 8 + m) * OUT_F + rowB0 + tx * 8;
        float4 v0 = make_float4(acc[m][0] + bb[0], acc[m][1] + bb[1],
                                acc[m][2] + bb[2], acc[m][3] + bb[3]);
        float4 v1 = make_float4(acc[m][4] + bb[4], acc[m][5] + bb[5],
                                acc[m][6] + bb[6], acc[m][7] + bb[7]);
        *reinterpret_cast<float4*>(row)     = v0;
        *reinterpret_cast<float4*>(row + 4) = v1;
    }
}

// ============================================================
extern "C" void kernel_launch(void* const* d_in, const int* in_sizes, int n_in,
                              void* d_out, int out_size) {
    const float* x    = (const float*)d_in[0];   // [8,512,1024]
    const float* sp   = (const float*)d_in[1];   // [8,16]
    const float* W    = (const float*)d_in[2];   // [16,1024,1024]
    const float* bias = (const float*)d_in[3];   // [16,1024]
    float* out = (float*)d_out;                  // [8,512,1024]

    // 1) mix weights: 262144 float4 positions
    mix_weights_kernel<<<(OUT_F * IN_F / 4) / 256, 256>>>(W, sp);

    // 2) mix bias: 8192 elements
    mix_bias_kernel<<<(BATCH * OUT_F) / 256, 256>>>(bias, sp);

    // 3) batched GEMM with fused bias
    dim3 grid(OUT_F / BN, A_DIM / BM, BATCH);    // (8, 4, 8)
    gemm_kernel<<<grid, 256>>>(x, out);
}

// round 3
// speedup vs baseline: 1.0035x; 1.0035x over previous
#include <cuda_runtime.h>
#include <cuda_bf16.h>

#define N_OPT 16
#define OUT_F 1024
#define IN_F  1024
#define BATCH 8
#define A_DIM 512

// ---- scratch (device globals: no alloc in kernel_launch) ----
__device__ float g_wmix[BATCH * OUT_F * IN_F];   // 32 MB: per-batch mixed weights [b][i][j]
__device__ float g_bmix[BATCH * OUT_F];          // per-batch mixed bias

// ============================================================
// Kernel 1: w_mixed[b][i][j] = sum_n sp[b][n] * W[n][i][j]
// Each thread owns one float4 position of the [OUT_F*IN_F] plane,
// reads the 16 expert values ONCE, accumulates all 8 batches.
// Traffic: 64 MB read + 32 MB write.
// ============================================================
__global__ void mix_weights_kernel(const float* __restrict__ W,
                                   const float* __restrict__ sp) {
    __shared__ float s_sp[BATCH * N_OPT];
    if (threadIdx.x < BATCH * N_OPT) s_sp[threadIdx.x] = sp[threadIdx.x];
    __syncthreads();

    const int t = blockIdx.x * blockDim.x + threadIdx.x;    // float4 index in plane
    const int plane4 = (OUT_F * IN_F) / 4;                  // 262144
    if (t >= plane4) return;

    const float4* W4 = reinterpret_cast<const float4*>(W);

    float4 acc[BATCH];
#pragma unroll
    for (int b = 0; b < BATCH; b++) acc[b] = make_float4(0.f, 0.f, 0.f, 0.f);

#pragma unroll
    for (int n = 0; n < N_OPT; n++) {
        float4 w = W4[(size_t)n * plane4 + t];
#pragma unroll
        for (int b = 0; b < BATCH; b++) {
            float s = s_sp[b * N_OPT + n];
            acc[b].x += s * w.x;
            acc[b].y += s * w.y;
            acc[b].z += s * w.z;
            acc[b].w += s * w.w;
        }
    }

    float4* out4 = reinterpret_cast<float4*>(g_wmix);
#pragma unroll
    for (int b = 0; b < BATCH; b++) out4[(size_t)b * plane4 + t] = acc[b];
}

// ============================================================
// Kernel 2: b_mixed[b][i] = sum_n sp[b][n] * bias[n][i]
// ============================================================
__global__ void mix_bias_kernel(const float* __restrict__ bias,
                                const float* __restrict__ sp) {
    int tid = blockIdx.x * blockDim.x + threadIdx.x;   // [0, BATCH*OUT_F)
    if (tid >= BATCH * OUT_F) return;
    int b = tid / OUT_F;
    int i = tid % OUT_F;
    float acc = 0.f;
#pragma unroll
    for (int n = 0; n < N_OPT; n++) acc += sp[b * N_OPT + n] * bias[n * OUT_F + i];
    g_bmix[tid] = acc;
}

// ============================================================
// Kernel 3: batched SGEMM (NT): out[b][a][i] = sum_j x[b][a][j]*w_mixed[b][i][j] + b_mixed[b][i]
// Tiles: BM=128 (a), BN=128 (i), BK=16 (j). 256 threads, 8x8 per thread.
// ============================================================
#define BM 128
#define BN 128
#define BK 16

__global__ void __launch_bounds__(256, 2)
gemm_kernel(const float* __restrict__ x, float* __restrict__ out) {
    const int b  = blockIdx.z;
    const float* Ag = x + (size_t)b * A_DIM * IN_F;                 // [512,1024]
    const float* Bg = g_wmix + (size_t)b * OUT_F * IN_F;            // [1024,1024]

    __shared__ float As[BK][BM + 1];
    __shared__ float Bs[BK][BN + 1];

    const int tid = threadIdx.x;
    const int tx = tid & 15;       // 0..15 -> N direction
    const int ty = tid >> 4;       // 0..15 -> M direction

    const int rowA0 = blockIdx.y * BM;    // a offset
    const int rowB0 = blockIdx.x * BN;    // i offset

    float acc[8][8];
#pragma unroll
    for (int m = 0; m < 8; m++)
#pragma unroll
        for (int n = 0; n < 8; n++) acc[m][n] = 0.f;

    for (int k0 = 0; k0 < IN_F; k0 += BK) {
        // load tiles: 128 rows x 16 cols = 512 float4 each; 256 threads x 2
#pragma unroll
        for (int i = 0; i < 2; i++) {
            int idx = tid + i * 256;          // 0..511
            int r   = idx >> 2;               // 0..127
            int c4  = idx & 3;                // 0..3
            float4 va = *reinterpret_cast<const float4*>(
                Ag + (size_t)(rowA0 + r) * IN_F + k0 + c4 * 4);
            As[c4 * 4 + 0][r] = va.x;
            As[c4 * 4 + 1][r] = va.y;
            As[c4 * 4 + 2][r] = va.z;
            As[c4 * 4 + 3][r] = va.w;
            float4 vb = *reinterpret_cast<const float4*>(
                Bg + (size_t)(rowB0 + r) * IN_F + k0 + c4 * 4);
            Bs[c4 * 4 + 0][r] = vb.x;
            Bs[c4 * 4 + 1][r] = vb.y;
            Bs[c4 * 4 + 2][r] = vb.z;
            Bs[c4 * 4 + 3][r] = vb.w;
        }
        __syncthreads();

#pragma unroll
        for (int k = 0; k < BK; k++) {
            float af[8], bf[8];
#pragma unroll
            for (int m = 0; m < 8; m++) af[m] = As[k][ty * 8 + m];
#pragma unroll
            for (int n = 0; n < 8; n++) bf[n] = Bs[k][tx * 8 + n];
#pragma unroll
            for (int m = 0; m < 8; m++)
#pragma unroll
                for (int n = 0; n < 8; n++) acc[m][n] += af[m] * bf[n];
        }
        __syncthreads();
    }

    // epilogue: add mixed bias, vectorized stores
    const float* bm = g_bmix + (size_t)b * OUT_F;
    float bb[8];
#pragma unroll
    for (int n = 0; n < 8; n++) bb[n] = bm[rowB0 + tx * 8 + n];

    float* Og = out + (size_t)b * A_DIM * OUT_F;
#pragma unroll
    for (int m = 0; m < 8; m++) {
        float* row = Og + (size_t)(rowA0 + ty * 8 + m) * OUT_F + rowB0 + tx * 8;
        float4 v0 = make_float4(acc[m][0] + bb[0], acc[m][1] + bb[1],
                                acc[m][2] + bb[2], acc[m][3] + bb[3]);
        float4 v1 = make_float4(acc[m][4] + bb[4], acc[m][5] + bb[5],
                                acc[m][6] + bb[6], acc[m][7] + bb[7]);
        *reinterpret_cast<float4*>(row)     = v0;
        *reinterpret_cast<float4*>(row + 4) = v1;
    }
}

// ============================================================
extern "C" void kernel_launch(void* const* d_in, const int* in_sizes, int n_in,
                              void* d_out, int out_size) {
    const float* x    = (const float*)d_in[0];   // [8,512,1024]
    const float* sp   = (const float*)d_in[1];   // [8,16]
    const float* W    = (const float*)d_in[2];   // [16,1024,1024]
    const float* bias = (const float*)d_in[3];   // [16,1024]
    float* out = (float*)d_out;                  // [8,512,1024]

    // 1) mix weights: 262144 float4 positions
    mix_weights_kernel<<<(OUT_F * IN_F / 4) / 256, 256>>>(W, sp);

    // 2) mix bias: 8192 elements
    mix_bias_kernel<<<(BATCH * OUT_F) / 256, 256>>>(bias, sp);

    // 3) batched GEMM with fused bias
    dim3 grid(OUT_F / BN, A_DIM / BM, BATCH);    // (8, 4, 8)
    gemm_kernel<<<grid, 256>>>(x, out);
}

// round 5
// speedup vs baseline: 2.9834x; 2.9731x over previous
#include <cuda_runtime.h>
#include <cuda_bf16.h>
#include <cstdint>

#define N_OPT 16
#define OUT_F 1024
#define IN_F  1024
#define BATCH 8
#define A_DIM 512

// GEMM tiling
#define BM 128
#define BN 256
#define BKC 32                    // bf16 K per stage
#define NSTAGE 4
#define NKC (IN_F / BKC)          // 32 stages of K
#define MT (A_DIM / BM)           // 4
#define NTG (OUT_F / BN)          // 4

#define A_BLK_BYTES (BM * 128)    // 16384: 128 rows x [hi 64B | lo 64B]
#define B_BLK_BYTES (BN * 128)    // 32768
#define STAGE_BYTES (A_BLK_BYTES + B_BLK_BYTES)   // 49152
#define SMEM_BYTES  (1024 + NSTAGE * STAGE_BYTES) // 197632

// ---- scratch (device globals; no allocation anywhere) ----
// staged, swizzled, hi/lo-interleaved operands
__device__ __align__(1024) __nv_bfloat16 g_xs[BATCH * A_DIM * IN_F * 2];  // 16 MB
__device__ __align__(1024) __nv_bfloat16 g_ws[BATCH * OUT_F * IN_F * 2];  // 32 MB
__device__ float g_bmix[BATCH * OUT_F];

// ================= PTX helpers (all plain-sm_103-safe) =================
__device__ __forceinline__ uint32_t smem_u32(const void* p) {
    uint32_t a;
    asm("{ .reg .u64 t; cvta.to.shared.u64 t, %1; cvt.u32.u64 %0, t; }" : "=r"(a) : "l"(p));
    return a;
}
#define MBAR_INIT(addr, cnt) \
    asm volatile("mbarrier.init.shared.b64 [%0], %1;" :: "r"(addr), "r"(cnt) : "memory")
#define MBAR_EXPECT_TX(addr, bytes) \
    asm volatile("mbarrier.arrive.expect_tx.shared.b64 _, [%0], %1;" :: "r"(addr), "r"(bytes) : "memory")
#define MBAR_ARRIVE(addr) \
    asm volatile("mbarrier.arrive.shared.b64 _, [%0];" :: "r"(addr) : "memory")
__device__ __forceinline__ void mbar_wait(uint32_t mbar, uint32_t parity) {
    asm volatile(
        "{\n\t.reg .pred P;\n\t"
        "WL_%=:\n\t"
        "mbarrier.try_wait.parity.acquire.cta.shared::cta.b64 P, [%0], %1, 0x989680;\n\t"
        "@!P bra WL_%=;\n\t}"
        :: "r"(mbar), "r"(parity) : "memory");
}
#define BULK_G2S(dst, src, bytes, mbar) \
    asm volatile("cp.async.bulk.shared::cluster.global.mbarrier::complete_tx::bytes [%0], [%1], %2, [%3];" \
                 :: "r"(dst), "l"(src), "r"(bytes), "r"(mbar) : "memory")

__device__ __forceinline__ void ldsm_x4(uint32_t* r, uint32_t addr) {
    asm volatile("ldmatrix.sync.aligned.m8n8.x4.shared.b16 {%0,%1,%2,%3}, [%4];"
        : "=r"(r[0]), "=r"(r[1]), "=r"(r[2]), "=r"(r[3]) : "r"(addr));
}
__device__ __forceinline__ void mma_bf16(float* d, const uint32_t* a, const uint32_t* b) {
    asm volatile(
        "mma.sync.aligned.m16n8k16.row.col.f32.bf16.bf16.f32 "
        "{%0,%1,%2,%3}, {%4,%5,%6,%7}, {%8,%9}, {%0,%1,%2,%3};"
        : "+f"(d[0]), "+f"(d[1]), "+f"(d[2]), "+f"(d[3])
        : "r"(a[0]), "r"(a[1]), "r"(a[2]), "r"(a[3]), "r"(b[0]), "r"(b[1]));
}

__device__ __forceinline__ uint32_t pk2(__nv_bfloat16 a, __nv_bfloat16 b) {
    __nv_bfloat162 t(a, b);
    return *reinterpret_cast<uint32_t*>(&t);
}

// ============================================================
// Kernel 1: mix weights -> staged hi/lo bf16.
// Staged layout: block(b, nt, kc) = ((b*4+nt)*32+kc), 32 KB each:
//   row r (=out-feature & 255), 128B: [hi k0..31 | lo k0..31],
//   16B chunk c stored at (c ^ (r&7)).
// ============================================================
__global__ void mix_weights_kernel(const float* __restrict__ W,
                                   const float* __restrict__ sp) {
    __shared__ float s_sp[BATCH * N_OPT];
    if (threadIdx.x < BATCH * N_OPT) s_sp[threadIdx.x] = sp[threadIdx.x];
    __syncthreads();

    const int t = blockIdx.x * blockDim.x + threadIdx.x;   // float4 index in 1024x1024 plane
    const int plane4 = (OUT_F * IN_F) / 4;
    const float4* W4 = reinterpret_cast<const float4*>(W);

    float4 acc[BATCH];
#pragma unroll
    for (int b = 0; b < BATCH; b++) acc[b] = make_float4(0.f, 0.f, 0.f, 0.f);
#pragma unroll
    for (int n = 0; n < N_OPT; n++) {
        float4 w = W4[(size_t)n * plane4 + t];
#pragma unroll
        for (int b = 0; b < BATCH; b++) {
            float s = s_sp[b * N_OPT + n];
            acc[b].x += s * w.x; acc[b].y += s * w.y;
            acc[b].z += s * w.z; acc[b].w += s * w.w;
        }
    }

    const int i  = t >> 8;                 // out feature 0..1023
    const int j0 = (t & 255) * 4;          // k
    const int nt = i >> 8, r = i & 255;
    const int kc = j0 >> 5;                // stage chunk
    const int kk = j0 & 31;
    const int ch = kk >> 3;                // 16B chunk within hi half (0..3)
    const int sub = (kk & 7) * 2;          // byte offset within chunk (0 or 8)
    const uint32_t off_h = (uint32_t)r * 128 + (uint32_t)((ch       ^ (r & 7)) * 16) + sub;
    const uint32_t off_l = (uint32_t)r * 128 + (uint32_t)(((ch + 4) ^ (r & 7)) * 16) + sub;
    char* base = (char*)g_ws;

#pragma unroll
    for (int b = 0; b < BATCH; b++) {
        float4 v = acc[b];
        __nv_bfloat16 h0 = __float2bfloat16(v.x), h1 = __float2bfloat16(v.y);
        __nv_bfloat16 h2 = __float2bfloat16(v.z), h3 = __float2bfloat16(v.w);
        __nv_bfloat16 l0 = __float2bfloat16(v.x - __bfloat162float(h0));
        __nv_bfloat16 l1 = __float2bfloat16(v.y - __bfloat162float(h1));
        __nv_bfloat16 l2 = __float2bfloat16(v.z - __bfloat162float(h2));
        __nv_bfloat16 l3 = __float2bfloat16(v.w - __bfloat162float(h3));
        size_t blk = ((size_t)(b * NTG + nt) * NKC + kc) * B_BLK_BYTES;
        *reinterpret_cast<uint2*>(base + blk + off_h) = make_uint2(pk2(h0, h1), pk2(h2, h3));
        *reinterpret_cast<uint2*>(base + blk + off_l) = make_uint2(pk2(l0, l1), pk2(l2, l3));
    }
}

// ============================================================
// Kernel 2: convert x -> staged hi/lo bf16 (16 KB blocks, 128 rows).
// ============================================================
__global__ void convert_x_kernel(const float* __restrict__ x) {
    const int t = blockIdx.x * blockDim.x + threadIdx.x;
    const int per_b = (A_DIM * IN_F) / 4;                    // 131072
    const int b = t / per_b;
    const int rem = t % per_b;
    const int a  = rem >> 8;
    const int j0 = (rem & 255) * 4;
    const int mt = a >> 7, r = a & 127;
    const int kc = j0 >> 5;
    const int kk = j0 & 31;
    const int ch = kk >> 3;
    const int sub = (kk & 7) * 2;

    float4 v = reinterpret_cast<const float4*>(x)[t];
    __nv_bfloat16 h0 = __float2bfloat16(v.x), h1 = __float2bfloat16(v.y);
    __nv_bfloat16 h2 = __float2bfloat16(v.z), h3 = __float2bfloat16(v.w);
    __nv_bfloat16 l0 = __float2bfloat16(v.x - __bfloat162float(h0));
    __nv_bfloat16 l1 = __float2bfloat16(v.y - __bfloat162float(h1));
    __nv_bfloat16 l2 = __float2bfloat16(v.z - __bfloat162float(h2));
    __nv_bfloat16 l3 = __float2bfloat16(v.w - __bfloat162float(h3));

    const uint32_t off_h = (uint32_t)r * 128 + (uint32_t)((ch       ^ (r & 7)) * 16) + sub;
    const uint32_t off_l = (uint32_t)r * 128 + (uint32_t)(((ch + 4) ^ (r & 7)) * 16) + sub;
    size_t blk = ((size_t)(b * MT + mt) * NKC + kc) * A_BLK_BYTES;
    char* base = (char*)g_xs;
    *reinterpret_cast<uint2*>(base + blk + off_h) = make_uint2(pk2(h0, h1), pk2(h2, h3));
    *reinterpret_cast<uint2*>(base + blk + off_l) = make_uint2(pk2(l0, l1), pk2(l2, l3));
}

// ============================================================
// Kernel 3: bias mix
// ============================================================
__global__ void mix_bias_kernel(const float* __restrict__ bias,
                                const float* __restrict__ sp) {
    int tid = blockIdx.x * blockDim.x + threadIdx.x;
    if (tid >= BATCH * OUT_F) return;
    int b = tid / OUT_F, i = tid % OUT_F;
    float acc = 0.f;
#pragma unroll
    for (int n = 0; n < N_OPT; n++) acc += sp[b * N_OPT + n] * bias[n * OUT_F + i];
    g_bmix[tid] = acc;
}

// ============================================================
// Kernel 4: HMMA GEMM, split-bf16 (hh + hl + lh), cp.async.bulk 4-stage pipe.
// CTA 128x256, 8 warps (2x4), warp 64x64. grid (4,4,8) = 128 CTAs.
// ============================================================
__global__ void __launch_bounds__(256, 1)
gemm_mma_kernel(float* __restrict__ out) {
    extern __shared__ char dsmem[];
    const uint32_t sbase = smem_u32(dsmem);
    const uint32_t data  = (sbase + 64 + 1023u) & ~1023u;
    uint32_t mb_full[NSTAGE], mb_empty[NSTAGE];
#pragma unroll
    for (int s = 0; s < NSTAGE; s++) { mb_full[s] = sbase + s * 8; mb_empty[s] = sbase + 32 + s * 8; }

    const int tid = threadIdx.x, lane = tid & 31, wid = tid >> 5;
    const int wm = wid >> 2, wn = wid & 3;
    const int nt = blockIdx.x, mt = blockIdx.y, b = blockIdx.z;

    const char* Ag = (const char*)g_xs + (size_t)((b * MT + mt) * NKC) * A_BLK_BYTES;
    const char* Bg = (const char*)g_ws + (size_t)((b * NTG + nt) * NKC) * B_BLK_BYTES;

    if (tid == 0) {
#pragma unroll
        for (int s = 0; s < NSTAGE; s++) { MBAR_INIT(mb_full[s], 1); MBAR_INIT(mb_empty[s], 8); }
    }
    __syncthreads();

    if (tid == 0) {
#pragma unroll
        for (int p = 0; p < NSTAGE - 1; p++) {
            MBAR_EXPECT_TX(mb_full[p], STAGE_BYTES);
            BULK_G2S(data + p * STAGE_BYTES,               Ag + (size_t)p * A_BLK_BYTES, A_BLK_BYTES, mb_full[p]);
            BULK_G2S(data + p * STAGE_BYTES + A_BLK_BYTES, Bg + (size_t)p * B_BLK_BYTES, B_BLK_BYTES, mb_full[p]);
        }
    }

    // per-lane ldmatrix address components
    const int a_row0 = wm * 64 + (lane & 15);
    const int a_csel = lane >> 4;                         // +0 / +1 chunk (k0-7 vs k8-15)
    const int b_row0 = wn * 64 + (lane & 7) + ((lane >> 4) << 3);
    const int b_csel = (lane >> 3) & 1;

    float acc[4][8][4];
#pragma unroll
    for (int mi = 0; mi < 4; mi++)
#pragma unroll
        for (int nj = 0; nj < 8; nj++)
#pragma unroll
            for (int q = 0; q < 4; q++) acc[mi][nj][q] = 0.f;

    for (int kc = 0; kc < NKC; kc++) {
        const int s = kc & (NSTAGE - 1);

        // producer refill (tid 0)
        if (tid == 0 && kc + NSTAGE - 1 < NKC) {
            const int q = kc + NSTAGE - 1;
            const int ps = q & (NSTAGE - 1);
            if (kc >= 1) mbar_wait(mb_empty[ps], ((kc - 1) >> 2) & 1);
            MBAR_EXPECT_TX(mb_full[ps], STAGE_BYTES);
            BULK_G2S(data + ps * STAGE_BYTES,               Ag + (size_t)q * A_BLK_BYTES, A_BLK_BYTES, mb_full[ps]);
            BULK_G2S(data + ps * STAGE_BYTES + A_BLK_BYTES, Bg + (size_t)q * B_BLK_BYTES, B_BLK_BYTES, mb_full[ps]);
        }

        mbar_wait(mb_full[s], (kc >> 2) & 1);

        const uint32_t Abase = data + s * STAGE_BYTES;
        const uint32_t Bbase = Abase + A_BLK_BYTES;

#pragma unroll
        for (int u = 0; u < 2; u++) {                     // two k16 sub-steps per stage
            uint32_t Ah[4][4], Al[4][4], Bh[4][4], Bl[4][4];
#pragma unroll
            for (int mi = 0; mi < 4; mi++) {
                int row = a_row0 + mi * 16;
                int ch_h = (0 + u * 2 + a_csel) ^ (row & 7);
                int ch_l = (4 + u * 2 + a_csel) ^ (row & 7);
                ldsm_x4(Ah[mi], Abase + row * 128 + ch_h * 16);
                ldsm_x4(Al[mi], Abase + row * 128 + ch_l * 16);
            }
#pragma unroll
            for (int ni = 0; ni < 4; ni++) {
                int row = b_row0 + ni * 16;
                int ch_h = (0 + u * 2 + b_csel) ^ (row & 7);
                int ch_l = (4 + u * 2 + b_csel) ^ (row & 7);
                ldsm_x4(Bh[ni], Bbase + row * 128 + ch_h * 16);
                ldsm_x4(Bl[ni], Bbase + row * 128 + ch_l * 16);
            }
            if (u == 1 && lane == 0) MBAR_ARRIVE(mb_empty[s]);   // all slot reads done

#pragma unroll
            for (int mi = 0; mi < 4; mi++)
#pragma unroll
                for (int ni = 0; ni < 4; ni++)
#pragma unroll
                    for (int jj = 0; jj < 2; jj++) {
                        const int nj = ni * 2 + jj;
                        mma_bf16(acc[mi][nj], Ah[mi], &Bh[ni][jj * 2]);
                        mma_bf16(acc[mi][nj], Ah[mi], &Bl[ni][jj * 2]);
                        mma_bf16(acc[mi][nj], Al[mi], &Bh[ni][jj * 2]);
                    }
        }
    }

    // epilogue: add mixed bias, store
    const int ncol_base = nt * BN + wn * 64;
    const float* bm = g_bmix + b * OUT_F + ncol_base;
    float* Ob = out + (size_t)b * A_DIM * OUT_F;

#pragma unroll
    for (int mi = 0; mi < 4; mi++) {
        const int arow = mt * BM + wm * 64 + mi * 16 + (lane >> 2);
        float* r0 = Ob + (size_t)arow * OUT_F + ncol_base;
        float* r1 = r0 + 8 * OUT_F;
#pragma unroll
        for (int nj = 0; nj < 8; nj++) {
            const int nc = nj * 8 + 2 * (lane & 3);
            float2 bb = *reinterpret_cast<const float2*>(bm + nc);
            float2 v0 = make_float2(acc[mi][nj][0] + bb.x, acc[mi][nj][1] + bb.y);
            float2 v1 = make_float2(acc[mi][nj][2] + bb.x, acc[mi][nj][3] + bb.y);
            *reinterpret_cast<float2*>(r0 + nc) = v0;
            *reinterpret_cast<float2*>(r1 + nc) = v1;
        }
    }
}

// ============================================================
extern "C" void kernel_launch(void* const* d_in, const int* in_sizes, int n_in,
                              void* d_out, int out_size) {
    const float* x    = (const float*)d_in[0];   // [8,512,1024]
    const float* sp   = (const float*)d_in[1];   // [8,16]
    const float* W    = (const float*)d_in[2];   // [16,1024,1024]
    const float* bias = (const float*)d_in[3];   // [16,1024]
    float* out = (float*)d_out;                  // [8,512,1024]

    cudaFuncSetAttribute(gemm_mma_kernel,
                         cudaFuncAttributeMaxDynamicSharedMemorySize, SMEM_BYTES);

    mix_weights_kernel<<<(OUT_F * IN_F / 4) / 256, 256>>>(W, sp);
    convert_x_kernel<<<(BATCH * A_DIM * IN_F / 4) / 256, 256>>>(x);
    mix_bias_kernel<<<(BATCH * OUT_F + 255) / 256, 256>>>(bias, sp);

    dim3 grid(NTG, MT, BATCH);   // (4,4,8) = 128 CTAs
    gemm_mma_kernel<<<grid, 256, SMEM_BYTES>>>(out);
}

// round 6
// speedup vs baseline: 3.5249x; 1.1815x over previous
#include <cuda_runtime.h>
#include <cuda_bf16.h>
#include <cuda_fp16.h>
#include <cstdint>

#define N_OPT 16
#define OUT_F 1024
#define IN_F  1024
#define BATCH 8
#define A_DIM 512

// GEMM tiling
#define BM 128
#define BN 256
#define BKC 32                    // K elems per stage
#define NSTAGE 4
#define NKC (IN_F / BKC)          // 32
#define MT (A_DIM / BM)           // 4
#define NTG (OUT_F / BN)          // 4

#define A_BLK_BYTES (BM * 128)    // 16384: 128 rows x [fp16-hi 64B | bf16-lo 64B]
#define B_BLK_BYTES (BN * 128)    // 32768
#define STAGE_BYTES (A_BLK_BYTES + B_BLK_BYTES)   // 49152
#define SMEM_BYTES  (1024 + NSTAGE * STAGE_BYTES) // 197632

// ---- scratch (device globals; no allocation anywhere) ----
__device__ __align__(1024) __nv_bfloat16 g_xs[BATCH * A_DIM * IN_F * 2];  // 16 MB staged x (fp16 hi | bf16)
__device__ __align__(1024) __nv_bfloat16 g_ws[BATCH * OUT_F * IN_F * 2];  // 32 MB staged w (fp16 hi | bf16 lo)
__device__ float g_bmix[BATCH * OUT_F];

// ================= PTX helpers (plain-sm_103-safe) =================
__device__ __forceinline__ uint32_t smem_u32(const void* p) {
    uint32_t a;
    asm("{ .reg .u64 t; cvta.to.shared.u64 t, %1; cvt.u32.u64 %0, t; }" : "=r"(a) : "l"(p));
    return a;
}
#define MBAR_INIT(addr, cnt) \
    asm volatile("mbarrier.init.shared.b64 [%0], %1;" :: "r"(addr), "r"(cnt) : "memory")
#define MBAR_EXPECT_TX(addr, bytes) \
    asm volatile("mbarrier.arrive.expect_tx.shared.b64 _, [%0], %1;" :: "r"(addr), "r"(bytes) : "memory")
#define MBAR_ARRIVE(addr) \
    asm volatile("mbarrier.arrive.shared.b64 _, [%0];" :: "r"(addr) : "memory")
__device__ __forceinline__ void mbar_wait(uint32_t mbar, uint32_t parity) {
    asm volatile(
        "{\n\t.reg .pred P;\n\t"
        "WL_%=:\n\t"
        "mbarrier.try_wait.parity.acquire.cta.shared::cta.b64 P, [%0], %1, 0x989680;\n\t"
        "@!P bra WL_%=;\n\t}"
        :: "r"(mbar), "r"(parity) : "memory");
}
#define BULK_G2S(dst, src, bytes, mbar) \
    asm volatile("cp.async.bulk.shared::cluster.global.mbarrier::complete_tx::bytes [%0], [%1], %2, [%3];" \
                 :: "r"(dst), "l"(src), "r"(bytes), "r"(mbar) : "memory")

__device__ __forceinline__ void ldsm_x4(uint32_t* r, uint32_t addr) {
    asm volatile("ldmatrix.sync.aligned.m8n8.x4.shared.b16 {%0,%1,%2,%3}, [%4];"
        : "=r"(r[0]), "=r"(r[1]), "=r"(r[2]), "=r"(r[3]) : "r"(addr));
}
__device__ __forceinline__ void mma_bf16(float* d, const uint32_t* a, const uint32_t* b) {
    asm volatile(
        "mma.sync.aligned.m16n8k16.row.col.f32.bf16.bf16.f32 "
        "{%0,%1,%2,%3}, {%4,%5,%6,%7}, {%8,%9}, {%0,%1,%2,%3};"
        : "+f"(d[0]), "+f"(d[1]), "+f"(d[2]), "+f"(d[3])
        : "r"(a[0]), "r"(a[1]), "r"(a[2]), "r"(a[3]), "r"(b[0]), "r"(b[1]));
}
__device__ __forceinline__ void mma_f16(float* d, const uint32_t* a, const uint32_t* b) {
    asm volatile(
        "mma.sync.aligned.m16n8k16.row.col.f32.f16.f16.f32 "
        "{%0,%1,%2,%3}, {%4,%5,%6,%7}, {%8,%9}, {%0,%1,%2,%3};"
        : "+f"(d[0]), "+f"(d[1]), "+f"(d[2]), "+f"(d[3])
        : "r"(a[0]), "r"(a[1]), "r"(a[2]), "r"(a[3]), "r"(b[0]), "r"(b[1]));
}

__device__ __forceinline__ uint32_t pk2b(float a, float b) {
    __nv_bfloat162 t = __floats2bfloat162_rn(a, b);
    return *reinterpret_cast<uint32_t*>(&t);
}
__device__ __forceinline__ uint32_t pk2h(float a, float b) {
    __half2 t = __floats2half2_rn(a, b);
    return *reinterpret_cast<uint32_t*>(&t);
}

// ============================================================
// Kernel 1: mix weights -> staged [fp16 hi | bf16 lo].
// Staged layout: block(b, nt, kc), 32 KB: row r (out feat & 255), 128B row:
//   hi chunks ch 0..3 at (ch ^ (r&7))*16, lo chunks at ((ch+4) ^ (r&7))*16.
// Each thread handles 8 consecutive k of one row (2x float4 loads / expert).
// ============================================================
__global__ void mix_weights_kernel(const float* __restrict__ W,
                                   const float* __restrict__ sp) {
    __shared__ float s_sp[BATCH * N_OPT];
    if (threadIdx.x < BATCH * N_OPT) s_sp[threadIdx.x] = sp[threadIdx.x];
    __syncthreads();

    const int t = blockIdx.x * blockDim.x + threadIdx.x;   // 8-elem group in plane
    const int i  = t >> 7;                 // out feature 0..1023
    const int k0 = (t & 127) * 8;
    const int nt = i >> 8, r = i & 255;
    const int kc = k0 >> 5;
    const int ch = (k0 & 31) >> 3;

    const int plane4 = (OUT_F * IN_F) / 4;
    const float4* W4 = reinterpret_cast<const float4*>(W);

    float acc[BATCH][8];
#pragma unroll
    for (int b = 0; b < BATCH; b++)
#pragma unroll
        for (int q = 0; q < 8; q++) acc[b][q] = 0.f;

#pragma unroll
    for (int n = 0; n < N_OPT; n++) {
        float4 w0 = W4[(size_t)n * plane4 + t * 2];
        float4 w1 = W4[(size_t)n * plane4 + t * 2 + 1];
#pragma unroll
        for (int b = 0; b < BATCH; b++) {
            float s = s_sp[b * N_OPT + n];
            acc[b][0] += s * w0.x; acc[b][1] += s * w0.y;
            acc[b][2] += s * w0.z; acc[b][3] += s * w0.w;
            acc[b][4] += s * w1.x; acc[b][5] += s * w1.y;
            acc[b][6] += s * w1.z; acc[b][7] += s * w1.w;
        }
    }

    const uint32_t off_h = (uint32_t)r * 128 + (uint32_t)((ch       ^ (r & 7)) * 16);
    const uint32_t off_l = (uint32_t)r * 128 + (uint32_t)(((ch + 4) ^ (r & 7)) * 16);
    char* base = (char*)g_ws;

#pragma unroll
    for (int b = 0; b < BATCH; b++) {
        float hf[8], lf[8];
#pragma unroll
        for (int q = 0; q < 8; q++) {
            __half h = __float2half_rn(acc[b][q]);
            hf[q] = __half2float(h);
            lf[q] = acc[b][q] - hf[q];
        }
        uint4 hi = make_uint4(pk2h(acc[b][0], acc[b][1]), pk2h(acc[b][2], acc[b][3]),
                              pk2h(acc[b][4], acc[b][5]), pk2h(acc[b][6], acc[b][7]));
        uint4 lo = make_uint4(pk2b(lf[0], lf[1]), pk2b(lf[2], lf[3]),
                              pk2b(lf[4], lf[5]), pk2b(lf[6], lf[7]));
        size_t blk = ((size_t)(b * NTG + nt) * NKC + kc) * B_BLK_BYTES;
        *reinterpret_cast<uint4*>(base + blk + off_h) = hi;
        *reinterpret_cast<uint4*>(base + blk + off_l) = lo;
    }
}

// ============================================================
// Kernel 2: convert x -> staged [fp16(x) hi | bf16(x) lo] (16 KB blocks).
// ============================================================
__global__ void convert_x_kernel(const float* __restrict__ x) {
    const int t = blockIdx.x * blockDim.x + threadIdx.x;     // 8-elem group
    const int per_b8 = (A_DIM * IN_F) / 8;                   // 65536
    const int b = t / per_b8;
    const int rem = t % per_b8;
    const int a  = rem >> 7;
    const int k0 = (rem & 127) * 8;
    const int mt = a >> 7, r = a & 127;
    const int kc = k0 >> 5;
    const int ch = (k0 & 31) >> 3;

    const float4* x4 = reinterpret_cast<const float4*>(x);
    float4 v0 = x4[t * 2], v1 = x4[t * 2 + 1];

    uint4 hi = make_uint4(pk2h(v0.x, v0.y), pk2h(v0.z, v0.w),
                          pk2h(v1.x, v1.y), pk2h(v1.z, v1.w));
    uint4 lo = make_uint4(pk2b(v0.x, v0.y), pk2b(v0.z, v0.w),
                          pk2b(v1.x, v1.y), pk2b(v1.z, v1.w));

    const uint32_t off_h = (uint32_t)r * 128 + (uint32_t)((ch       ^ (r & 7)) * 16);
    const uint32_t off_l = (uint32_t)r * 128 + (uint32_t)(((ch + 4) ^ (r & 7)) * 16);
    size_t blk = ((size_t)(b * MT + mt) * NKC + kc) * A_BLK_BYTES;
    char* base = (char*)g_xs;
    *reinterpret_cast<uint4*>(base + blk + off_h) = hi;
    *reinterpret_cast<uint4*>(base + blk + off_l) = lo;
}

// ============================================================
// Kernel 3: bias mix
// ============================================================
__global__ void mix_bias_kernel(const float* __restrict__ bias,
                                const float* __restrict__ sp) {
    int tid = blockIdx.x * blockDim.x + threadIdx.x;
    if (tid >= BATCH * OUT_F) return;
    int b = tid / OUT_F, i = tid % OUT_F;
    float acc = 0.f;
#pragma unroll
    for (int n = 0; n < N_OPT; n++) acc += sp[b * N_OPT + n] * bias[n * OUT_F + i];
    g_bmix[tid] = acc;
}

// ============================================================
// Kernel 4: HMMA GEMM, mixed 2-term split:
//   out = fp16(x)*fp16(w)  [mma.f16]  +  bf16(x)*bf16(w - fp16(w))  [mma.bf16]
// CTA 128x256, 8 warps (2x4), warp 64x64. cp.async.bulk 4-stage pipe.
// grid (4,4,8) = 128 CTAs, one wave.
// ============================================================
__global__ void __launch_bounds__(256, 1)
gemm_mma_kernel(float* __restrict__ out) {
    extern __shared__ char dsmem[];
    const uint32_t sbase = smem_u32(dsmem);
    const uint32_t data  = (sbase + 64 + 1023u) & ~1023u;
    uint32_t mb_full[NSTAGE], mb_empty[NSTAGE];
#pragma unroll
    for (int s = 0; s < NSTAGE; s++) { mb_full[s] = sbase + s * 8; mb_empty[s] = sbase + 32 + s * 8; }

    const int tid = threadIdx.x, lane = tid & 31, wid = tid >> 5;
    const int wm = wid >> 2, wn = wid & 3;
    const int nt = blockIdx.x, mt = blockIdx.y, b = blockIdx.z;

    const char* Ag = (const char*)g_xs + (size_t)((b * MT + mt) * NKC) * A_BLK_BYTES;
    const char* Bg = (const char*)g_ws + (size_t)((b * NTG + nt) * NKC) * B_BLK_BYTES;

    if (tid == 0) {
#pragma unroll
        for (int s = 0; s < NSTAGE; s++) { MBAR_INIT(mb_full[s], 1); MBAR_INIT(mb_empty[s], 8); }
    }
    __syncthreads();

    if (tid == 0) {
#pragma unroll
        for (int p = 0; p < NSTAGE - 1; p++) {
            MBAR_EXPECT_TX(mb_full[p], STAGE_BYTES);
            BULK_G2S(data + p * STAGE_BYTES,               Ag + (size_t)p * A_BLK_BYTES, A_BLK_BYTES, mb_full[p]);
            BULK_G2S(data + p * STAGE_BYTES + A_BLK_BYTES, Bg + (size_t)p * B_BLK_BYTES, B_BLK_BYTES, mb_full[p]);
        }
    }

    const int a_row0 = wm * 64 + (lane & 15);
    const int a_csel = lane >> 4;
    const int b_row0 = wn * 64 + (lane & 7) + ((lane >> 4) << 3);
    const int b_csel = (lane >> 3) & 1;

    float acc[4][8][4];
#pragma unroll
    for (int mi = 0; mi < 4; mi++)
#pragma unroll
        for (int nj = 0; nj < 8; nj++)
#pragma unroll
            for (int q = 0; q < 4; q++) acc[mi][nj][q] = 0.f;

    for (int kc = 0; kc < NKC; kc++) {
        const int s = kc & (NSTAGE - 1);

        if (tid == 0 && kc + NSTAGE - 1 < NKC) {
            const int q = kc + NSTAGE - 1;
            const int ps = q & (NSTAGE - 1);
            if (kc >= 1) mbar_wait(mb_empty[ps], ((kc - 1) >> 2) & 1);
            MBAR_EXPECT_TX(mb_full[ps], STAGE_BYTES);
            BULK_G2S(data + ps * STAGE_BYTES,               Ag + (size_t)q * A_BLK_BYTES, A_BLK_BYTES, mb_full[ps]);
            BULK_G2S(data + ps * STAGE_BYTES + A_BLK_BYTES, Bg + (size_t)q * B_BLK_BYTES, B_BLK_BYTES, mb_full[ps]);
        }

        mbar_wait(mb_full[s], (kc >> 2) & 1);

        const uint32_t Abase = data + s * STAGE_BYTES;
        const uint32_t Bbase = Abase + A_BLK_BYTES;

#pragma unroll
        for (int u = 0; u < 2; u++) {                     // two k16 sub-steps per stage
            uint32_t Ah[4][4], Ab[4][4], Bh[4][4], Bl[4][4];
#pragma unroll
            for (int mi = 0; mi < 4; mi++) {
                int row = a_row0 + mi * 16;
                int ch_h = (0 + u * 2 + a_csel) ^ (row & 7);
                int ch_l = (4 + u * 2 + a_csel) ^ (row & 7);
                ldsm_x4(Ah[mi], Abase + row * 128 + ch_h * 16);
                ldsm_x4(Ab[mi], Abase + row * 128 + ch_l * 16);
            }
#pragma unroll
            for (int ni = 0; ni < 4; ni++) {
                int row = b_row0 + ni * 16;
                int ch_h = (0 + u * 2 + b_csel) ^ (row & 7);
                int ch_l = (4 + u * 2 + b_csel) ^ (row & 7);
                ldsm_x4(Bh[ni], Bbase + row * 128 + ch_h * 16);
                ldsm_x4(Bl[ni], Bbase + row * 128 + ch_l * 16);
            }
            if (u == 1 && lane == 0) MBAR_ARRIVE(mb_empty[s]);

#pragma unroll
            for (int mi = 0; mi < 4; mi++)
#pragma unroll
                for (int ni = 0; ni < 4; ni++)
#pragma unroll
                    for (int jj = 0; jj < 2; jj++) {
                        const int nj = ni * 2 + jj;
                        mma_f16 (acc[mi][nj], Ah[mi], &Bh[ni][jj * 2]);
                        mma_bf16(acc[mi][nj], Ab[mi], &Bl[ni][jj * 2]);
                    }
        }
    }

    // epilogue: add mixed bias, store
    const int ncol_base = nt * BN + wn * 64;
    const float* bm = g_bmix + b * OUT_F + ncol_base;
    float* Ob = out + (size_t)b * A_DIM * OUT_F;

#pragma unroll
    for (int mi = 0; mi < 4; mi++) {
        const int arow = mt * BM + wm * 64 + mi * 16 + (lane >> 2);
        float* r0 = Ob + (size_t)arow * OUT_F + ncol_base;
        float* r1 = r0 + 8 * OUT_F;
#pragma unroll
        for (int nj = 0; nj < 8; nj++) {
            const int nc = nj * 8 + 2 * (lane & 3);
            float2 bb = *reinterpret_cast<const float2*>(bm + nc);
            float2 v0 = make_float2(acc[mi][nj][0] + bb.x, acc[mi][nj][1] + bb.y);
            float2 v1 = make_float2(acc[mi][nj][2] + bb.x, acc[mi][nj][3] + bb.y);
            *reinterpret_cast<float2*>(r0 + nc) = v0;
            *reinterpret_cast<float2*>(r1 + nc) = v1;
        }
    }
}

// ============================================================
extern "C" void kernel_launch(void* const* d_in, const int* in_sizes, int n_in,
                              void* d_out, int out_size) {
    const float* x    = (const float*)d_in[0];   // [8,512,1024]
    const float* sp   = (const float*)d_in[1];   // [8,16]
    const float* W    = (const float*)d_in[2];   // [16,1024,1024]
    const float* bias = (const float*)d_in[3];   // [16,1024]
    float* out = (float*)d_out;                  // [8,512,1024]

    cudaFuncSetAttribute(gemm_mma_kernel,
                         cudaFuncAttributeMaxDynamicSharedMemorySize, SMEM_BYTES);

    mix_weights_kernel<<<(OUT_F * IN_F / 8) / 256, 256>>>(W, sp);
    convert_x_kernel<<<(BATCH * A_DIM * IN_F / 8) / 256, 256>>>(x);
    mix_bias_kernel<<<(BATCH * OUT_F + 255) / 256, 256>>>(bias, sp);

    dim3 grid(NTG, MT, BATCH);   // (4,4,8) = 128 CTAs, one wave
    gemm_mma_kernel<<<grid, 256, SMEM_BYTES>>>(out);
}

// round 7
// speedup vs baseline: 4.9086x; 1.3925x over previous
#include <cuda_runtime.h>
#include <cuda_bf16.h>
#include <cuda_fp16.h>
#include <cstdint>

#define N_OPT 16
#define OUT_F 1024
#define IN_F  1024
#define BATCH 8
#define A_DIM 512

// GEMM tiling
#define BM 128
#define BN 256
#define BKC 64                    // fp16 K elems per stage (one 128B row per M/N row)
#define NSTAGE 4
#define NKC (IN_F / BKC)          // 16
#define MT (A_DIM / BM)           // 4
#define NTG (OUT_F / BN)          // 4

#define A_BLK_BYTES (BM * 128)    // 16384: 128 rows x 64 fp16 (k-chunk)
#define B_BLK_BYTES (BN * 128)    // 32768
#define STAGE_BYTES (A_BLK_BYTES + B_BLK_BYTES)   // 49152
#define SMEM_BYTES  (1024 + NSTAGE * STAGE_BYTES) // 197632

// ---- scratch (device globals; no allocation anywhere) ----
__device__ __align__(1024) __half g_xs[BATCH * A_DIM * IN_F];   // 8 MB staged fp16 x
__device__ __align__(1024) __half g_ws[BATCH * OUT_F * IN_F];   // 16 MB staged fp16 w_mixed
__device__ float g_bmix[BATCH * OUT_F];

// ================= PTX helpers (plain-sm_103-safe) =================
__device__ __forceinline__ uint32_t smem_u32(const void* p) {
    uint32_t a;
    asm("{ .reg .u64 t; cvta.to.shared.u64 t, %1; cvt.u32.u64 %0, t; }" : "=r"(a) : "l"(p));
    return a;
}
#define MBAR_INIT(addr, cnt) \
    asm volatile("mbarrier.init.shared.b64 [%0], %1;" :: "r"(addr), "r"(cnt) : "memory")
#define MBAR_EXPECT_TX(addr, bytes) \
    asm volatile("mbarrier.arrive.expect_tx.shared.b64 _, [%0], %1;" :: "r"(addr), "r"(bytes) : "memory")
#define MBAR_ARRIVE(addr) \
    asm volatile("mbarrier.arrive.shared.b64 _, [%0];" :: "r"(addr) : "memory")
__device__ __forceinline__ void mbar_wait(uint32_t mbar, uint32_t parity) {
    asm volatile(
        "{\n\t.reg .pred P;\n\t"
        "WL_%=:\n\t"
        "mbarrier.try_wait.parity.acquire.cta.shared::cta.b64 P, [%0], %1, 0x989680;\n\t"
        "@!P bra WL_%=;\n\t}"
        :: "r"(mbar), "r"(parity) : "memory");
}
#define BULK_G2S(dst, src, bytes, mbar) \
    asm volatile("cp.async.bulk.shared::cluster.global.mbarrier::complete_tx::bytes [%0], [%1], %2, [%3];" \
                 :: "r"(dst), "l"(src), "r"(bytes), "r"(mbar) : "memory")

__device__ __forceinline__ void ldsm_x4(uint32_t* r, uint32_t addr) {
    asm volatile("ldmatrix.sync.aligned.m8n8.x4.shared.b16 {%0,%1,%2,%3}, [%4];"
        : "=r"(r[0]), "=r"(r[1]), "=r"(r[2]), "=r"(r[3]) : "r"(addr));
}
__device__ __forceinline__ void mma_f16(float* d, const uint32_t* a, const uint32_t* b) {
    asm volatile(
        "mma.sync.aligned.m16n8k16.row.col.f32.f16.f16.f32 "
        "{%0,%1,%2,%3}, {%4,%5,%6,%7}, {%8,%9}, {%0,%1,%2,%3};"
        : "+f"(d[0]), "+f"(d[1]), "+f"(d[2]), "+f"(d[3])
        : "r"(a[0]), "r"(a[1]), "r"(a[2]), "r"(a[3]), "r"(b[0]), "r"(b[1]));
}

__device__ __forceinline__ uint32_t pk2h(float a, float b) {
    __half2 t = __floats2half2_rn(a, b);
    return *reinterpret_cast<uint32_t*>(&t);
}

// ============================================================
// Kernel 1: mix weights -> staged fp16.
// Staged layout: block(b, nt, kc) of 32 KB, kc = k-chunk of 64 elems.
//   row r (= out-feature & 255) is 128 B: 8 chunks of 16B (8 fp16 each);
//   chunk ch (= (k&63)>>3) stored at byte (ch ^ (r&7))*16.
// Each thread handles 8 consecutive k of one row for all 8 batches.
// ============================================================
__global__ void mix_weights_kernel(const float* __restrict__ W,
                                   const float* __restrict__ sp) {
    __shared__ float s_sp[BATCH * N_OPT];
    if (threadIdx.x < BATCH * N_OPT) s_sp[threadIdx.x] = sp[threadIdx.x];
    __syncthreads();

    const int t = blockIdx.x * blockDim.x + threadIdx.x;   // 8-elem k-group in plane
    const int i  = t >> 7;                 // out feature 0..1023
    const int k0 = (t & 127) * 8;
    const int nt = i >> 8, r = i & 255;
    const int kc = k0 >> 6;
    const int ch = (k0 & 63) >> 3;

    const int plane4 = (OUT_F * IN_F) / 4;
    const float4* W4 = reinterpret_cast<const float4*>(W);

    float acc[BATCH][8];
#pragma unroll
    for (int b = 0; b < BATCH; b++)
#pragma unroll
        for (int q = 0; q < 8; q++) acc[b][q] = 0.f;

#pragma unroll
    for (int n = 0; n < N_OPT; n++) {
        float4 w0 = W4[(size_t)n * plane4 + t * 2];
        float4 w1 = W4[(size_t)n * plane4 + t * 2 + 1];
#pragma unroll
        for (int b = 0; b < BATCH; b++) {
            float s = s_sp[b * N_OPT + n];
            acc[b][0] += s * w0.x; acc[b][1] += s * w0.y;
            acc[b][2] += s * w0.z; acc[b][3] += s * w0.w;
            acc[b][4] += s * w1.x; acc[b][5] += s * w1.y;
            acc[b][6] += s * w1.z; acc[b][7] += s * w1.w;
        }
    }

    const uint32_t off = (uint32_t)r * 128 + (uint32_t)((ch ^ (r & 7)) * 16);
    char* base = (char*)g_ws;

#pragma unroll
    for (int b = 0; b < BATCH; b++) {
        uint4 hi = make_uint4(pk2h(acc[b][0], acc[b][1]), pk2h(acc[b][2], acc[b][3]),
                              pk2h(acc[b][4], acc[b][5]), pk2h(acc[b][6], acc[b][7]));
        size_t blk = ((size_t)(b * NTG + nt) * NKC + kc) * B_BLK_BYTES;
        *reinterpret_cast<uint4*>(base + blk + off) = hi;
    }
}

// ============================================================
// Kernel 2: convert x -> staged fp16 (16 KB blocks of 128 rows).
// ============================================================
__global__ void convert_x_kernel(const float* __restrict__ x) {
    const int t = blockIdx.x * blockDim.x + threadIdx.x;     // 8-elem k-group
    const int per_b8 = (A_DIM * IN_F) / 8;                   // 65536
    const int b = t / per_b8;
    const int rem = t % per_b8;
    const int a  = rem >> 7;
    const int k0 = (rem & 127) * 8;
    const int mt = a >> 7, r = a & 127;
    const int kc = k0 >> 6;
    const int ch = (k0 & 63) >> 3;

    const float4* x4 = reinterpret_cast<const float4*>(x);
    float4 v0 = x4[t * 2], v1 = x4[t * 2 + 1];

    uint4 hi = make_uint4(pk2h(v0.x, v0.y), pk2h(v0.z, v0.w),
                          pk2h(v1.x, v1.y), pk2h(v1.z, v1.w));

    const uint32_t off = (uint32_t)r * 128 + (uint32_t)((ch ^ (r & 7)) * 16);
    size_t blk = ((size_t)(b * MT + mt) * NKC + kc) * A_BLK_BYTES;
    char* base = (char*)g_xs;
    *reinterpret_cast<uint4*>(base + blk + off) = hi;
}

// ============================================================
// Kernel 3: bias mix
// ============================================================
__global__ void mix_bias_kernel(const float* __restrict__ bias,
                                const float* __restrict__ sp) {
    int tid = blockIdx.x * blockDim.x + threadIdx.x;
    if (tid >= BATCH * OUT_F) return;
    int b = tid / OUT_F, i = tid % OUT_F;
    float acc = 0.f;
#pragma unroll
    for (int n = 0; n < N_OPT; n++) acc += sp[b * N_OPT + n] * bias[n * OUT_F + i];
    g_bmix[tid] = acc;
}

// ============================================================
// Kernel 4: fp16 HMMA GEMM: out = fp16(x) * fp16(w_mixed)^T + bias
// CTA 128x256, 8 warps (2x4), warp 64x64. cp.async.bulk 4-stage pipe,
// 64 K-elems per stage (4 k16 sub-steps). grid (4,4,8) = 128 CTAs, one wave.
// ============================================================
__global__ void __launch_bounds__(256, 1)
gemm_mma_kernel(float* __restrict__ out) {
    extern __shared__ char dsmem[];
    const uint32_t sbase = smem_u32(dsmem);
    const uint32_t data  = (sbase + 64 + 1023u) & ~1023u;
    uint32_t mb_full[NSTAGE], mb_empty[NSTAGE];
#pragma unroll
    for (int s = 0; s < NSTAGE; s++) { mb_full[s] = sbase + s * 8; mb_empty[s] = sbase + 32 + s * 8; }

    const int tid = threadIdx.x, lane = tid & 31, wid = tid >> 5;
    const int wm = wid >> 2, wn = wid & 3;
    const int nt = blockIdx.x, mt = blockIdx.y, b = blockIdx.z;

    const char* Ag = (const char*)g_xs + (size_t)((b * MT + mt) * NKC) * A_BLK_BYTES;
    const char* Bg = (const char*)g_ws + (size_t)((b * NTG + nt) * NKC) * B_BLK_BYTES;

    if (tid == 0) {
#pragma unroll
        for (int s = 0; s < NSTAGE; s++) { MBAR_INIT(mb_full[s], 1); MBAR_INIT(mb_empty[s], 8); }
    }
    __syncthreads();

    if (tid == 0) {
#pragma unroll
        for (int p = 0; p < NSTAGE - 1; p++) {
            MBAR_EXPECT_TX(mb_full[p], STAGE_BYTES);
            BULK_G2S(data + p * STAGE_BYTES,               Ag + (size_t)p * A_BLK_BYTES, A_BLK_BYTES, mb_full[p]);
            BULK_G2S(data + p * STAGE_BYTES + A_BLK_BYTES, Bg + (size_t)p * B_BLK_BYTES, B_BLK_BYTES, mb_full[p]);
        }
    }

    const int a_row0 = wm * 64 + (lane & 15);
    const int a_csel = lane >> 4;
    const int b_row0 = wn * 64 + (lane & 7) + ((lane >> 4) << 3);
    const int b_csel = (lane >> 3) & 1;

    float acc[4][8][4];
#pragma unroll
    for (int mi = 0; mi < 4; mi++)
#pragma unroll
        for (int nj = 0; nj < 8; nj++)
#pragma unroll
            for (int q = 0; q < 4; q++) acc[mi][nj][q] = 0.f;

    for (int kc = 0; kc < NKC; kc++) {
        const int s = kc & (NSTAGE - 1);

        if (tid == 0 && kc + NSTAGE - 1 < NKC) {
            const int q = kc + NSTAGE - 1;
            const int ps = q & (NSTAGE - 1);
            if (kc >= 1) mbar_wait(mb_empty[ps], ((kc - 1) >> 2) & 1);
            MBAR_EXPECT_TX(mb_full[ps], STAGE_BYTES);
            BULK_G2S(data + ps * STAGE_BYTES,               Ag + (size_t)q * A_BLK_BYTES, A_BLK_BYTES, mb_full[ps]);
            BULK_G2S(data + ps * STAGE_BYTES + A_BLK_BYTES, Bg + (size_t)q * B_BLK_BYTES, B_BLK_BYTES, mb_full[ps]);
        }

        mbar_wait(mb_full[s], (kc >> 2) & 1);

        const uint32_t Abase = data + s * STAGE_BYTES;
        const uint32_t Bbase = Abase + A_BLK_BYTES;

#pragma unroll
        for (int u = 0; u < 4; u++) {                     // four k16 sub-steps per stage
            uint32_t Ah[4][4], Bh[4][4];
#pragma unroll
            for (int mi = 0; mi < 4; mi++) {
                int row = a_row0 + mi * 16;
                int ch = (u * 2 + a_csel) ^ (row & 7);
                ldsm_x4(Ah[mi], Abase + row * 128 + ch * 16);
            }
#pragma unroll
            for (int ni = 0; ni < 4; ni++) {
                int row = b_row0 + ni * 16;
                int ch = (u * 2 + b_csel) ^ (row & 7);
                ldsm_x4(Bh[ni], Bbase + row * 128 + ch * 16);
            }
            if (u == 3 && lane == 0) MBAR_ARRIVE(mb_empty[s]);

#pragma unroll
            for (int mi = 0; mi < 4; mi++)
#pragma unroll
                for (int ni = 0; ni < 4; ni++)
#pragma unroll
                    for (int jj = 0; jj < 2; jj++)
                        mma_f16(acc[mi][ni * 2 + jj], Ah[mi], &Bh[ni][jj * 2]);
        }
    }

    // epilogue: add mixed bias, store
    const int ncol_base = nt * BN + wn * 64;
    const float* bm = g_bmix + b * OUT_F + ncol_base;
    float* Ob = out + (size_t)b * A_DIM * OUT_F;

#pragma unroll
    for (int mi = 0; mi < 4; mi++) {
        const int arow = mt * BM + wm * 64 + mi * 16 + (lane >> 2);
        float* r0 = Ob + (size_t)arow * OUT_F + ncol_base;
        float* r1 = r0 + 8 * OUT_F;
#pragma unroll
        for (int nj = 0; nj < 8; nj++) {
            const int nc = nj * 8 + 2 * (lane & 3);
            float2 bb = *reinterpret_cast<const float2*>(bm + nc);
            float2 v0 = make_float2(acc[mi][nj][0] + bb.x, acc[mi][nj][1] + bb.y);
            float2 v1 = make_float2(acc[mi][nj][2] + bb.x, acc[mi][nj][3] + bb.y);
            *reinterpret_cast<float2*>(r0 + nc) = v0;
            *reinterpret_cast<float2*>(r1 + nc) = v1;
        }
    }
}

// ============================================================
extern "C" void kernel_launch(void* const* d_in, const int* in_sizes, int n_in,
                              void* d_out, int out_size) {
    const float* x    = (const float*)d_in[0];   // [8,512,1024]
    const float* sp   = (const float*)d_in[1];   // [8,16]
    const float* W    = (const float*)d_in[2];   // [16,1024,1024]
    const float* bias = (const float*)d_in[3];   // [16,1024]
    float* out = (float*)d_out;                  // [8,512,1024]

    cudaFuncSetAttribute(gemm_mma_kernel,
                         cudaFuncAttributeMaxDynamicSharedMemorySize, SMEM_BYTES);

    mix_weights_kernel<<<(OUT_F * IN_F / 8) / 256, 256>>>(W, sp);
    convert_x_kernel<<<(BATCH * A_DIM * IN_F / 8) / 256, 256>>>(x);
    mix_bias_kernel<<<(BATCH * OUT_F + 255) / 256, 256>>>(bias, sp);

    dim3 grid(NTG, MT, BATCH);   // (4,4,8) = 128 CTAs, one wave
    gemm_mma_kernel<<<grid, 256, SMEM_BYTES>>>(out);
}